// round 1
// baseline (speedup 1.0000x reference)
#include <cuda_runtime.h>

#define BATCH 32
#define CIN   3
#define HH    64
#define WW    64
#define HC    128
#define NCTA  128
#define NTHR  256

// smem layout (floats)
#define A_OFF   0                  // h_prev tile, (WW+1) x HC = 65*128 = 8320 (row 0 = zero pad)
#define W_OFF   8320               // weights, 256 x 128 = 32768
#define G_OFF   (8320 + 32768)     // gates, 128 x 65 = 8320
#define C_OFF   (G_OFF + 8320)     // cell state, 32 x 64 = 2048
#define X_OFF   (C_OFF + 2048)     // x row, 3 x 65 = 196 (padded)
#define WIS_OFF (X_OFF + 196)      // input weights, 2 x 3 x 128 = 768
#define B_OFF   (WIS_OFF + 768)    // fused bias, 128
#define SMEM_FLOATS (B_OFF + 128)  // 52548 floats = 210192 bytes

// Global scratch: ping-pong hidden state, layout [buf][b][w][ci]
__device__ float g_h[2][BATCH * WW * HC];
__device__ unsigned g_count = 0;
__device__ unsigned g_phase = 0;

__global__ __launch_bounds__(NTHR, 1)
void rowlstm_kernel(const float* __restrict__ x,
                    const float* __restrict__ W_is,
                    const float* __restrict__ b_is,
                    const float* __restrict__ W_ss,
                    const float* __restrict__ b_ss,
                    const float* __restrict__ h0,
                    const float* __restrict__ c0,
                    float* __restrict__ out)
{
    extern __shared__ float sm[];
    float* A_s  = sm + A_OFF;
    float* W_s  = sm + W_OFF;
    float* G_s  = sm + G_OFF;
    float* C_s  = sm + C_OFF;
    float* X_s  = sm + X_OFF;
    float* WI_s = sm + WIS_OFF;
    float* BI_s = sm + B_OFF;

    const int tid = threadIdx.x;
    const int b   = blockIdx.x >> 2;   // batch index
    const int t   = blockIdx.x & 3;    // ci-tile (32 hidden channels)

    // ---- one-time loads (persist across all 64 steps) ----
    // W_s[k][col]: k = tap*128 + ci (tap0 = left/w-1, tap1 = center/w; tap2 is masked off)
    // col -> global gate channel: group = col/32 (o,f,i,g), co = group*128 + t*32 + col%32
    for (int idx = tid; idx < 32768; idx += NTHR) {
        int k = idx >> 7, col = idx & 127;
        int tap = k >> 7, ci = k & 127;
        int co = (col >> 5) * HC + t * 32 + (col & 31);
        W_s[idx] = W_ss[(co * HC + ci) * 3 + tap];
    }
    for (int idx = tid; idx < 128; idx += NTHR) {
        int co = (idx >> 5) * HC + t * 32 + (idx & 31);
        BI_s[idx] = b_is[co] + b_ss[co];
    }
    for (int idx = tid; idx < 768; idx += NTHR) {
        int tap = idx / 384, rem = idx - tap * 384;
        int cin = rem >> 7, col = rem & 127;
        int co = (col >> 5) * HC + t * 32 + (col & 31);
        WI_s[idx] = W_is[(co * CIN + cin) * 3 + tap];
    }
    for (int idx = tid; idx < 2048; idx += NTHR) {
        int cl = idx >> 6, w = idx & 63;
        int cg = t * 32 + cl;
        C_s[cl * 64 + w] = c0[cg * WW + w];
        g_h[0][(b * WW + w) * HC + cg] = h0[cg * WW + w];   // broadcast init h
    }
    for (int idx = tid; idx < HC; idx += NTHR) A_s[idx] = 0.f;  // zero pad row (w = -1)
    if (tid < CIN) X_s[tid * 65] = 0.f;                          // x zero pad (w = -1)

    // ---- software grid barrier (sense via monotonically increasing phase) ----
    unsigned my_bar = 0;
    unsigned phase0 = 0;
    if (tid == 0) phase0 = *((volatile unsigned*)&g_phase);

    auto gsync = [&]() {
        __syncthreads();
        if (tid == 0) {
            my_bar++;
            __threadfence();
            unsigned v = atomicAdd(&g_count, 1);
            if (v == NCTA - 1) {
                atomicExch(&g_count, 0);
                __threadfence();
                atomicAdd(&g_phase, 1);
            } else {
                unsigned tgt = phase0 + my_bar;
                while ((int)(*((volatile unsigned*)&g_phase) - tgt) < 0) { }
                __threadfence();
            }
        }
        __syncthreads();
    };

    gsync();   // init h-state visible to all CTAs

    const int i_  = tid >> 4;          // 0..15: w-lane group
    const int j_  = tid & 15;          // 0..15: co group
    const int co0 = j_ << 3;           // 8 contiguous gate cols per thread
    const int ci_l = tid >> 3;         // recombine mapping: 0..31
    const int wb   = (tid & 7) << 3;   // 8 contiguous w per thread
    const int ci_g = t * 32 + ci_l;

    for (int s = 0; s < HH; s++) {
        const int r = s & 1;

        // load h_prev tile: A_s[w+1][ci] = g_h[r][b][w][ci]
        {
            const float4* hb = (const float4*)(g_h[r] + b * WW * HC);
            float4* Ad = (float4*)(A_s + HC);
            for (int idx = tid; idx < 2048; idx += NTHR) Ad[idx] = hb[idx];
        }
        // load x row for this step
        if (tid < CIN * WW) {
            int cin = tid >> 6, w = tid & 63;
            X_s[cin * 65 + 1 + w] = x[((b * CIN + cin) * HH + s) * WW + w];
        }
        __syncthreads();

        // ---- GEMM: gates[w][col] over K = 2 taps x 128 ci ----
        float acc[4][8];
        #pragma unroll
        for (int wi = 0; wi < 4; wi++)
            #pragma unroll
            for (int c = 0; c < 8; c++) acc[wi][c] = 0.f;

        #pragma unroll 4
        for (int ci = 0; ci < HC; ci++) {
            float aL[4], aC[4];
            #pragma unroll
            for (int wi = 0; wi < 4; wi++) {
                int wp = wi * 16 + i_;
                aL[wi] = A_s[wp * HC + ci];         // h_prev[w-1] (row 0 = zeros)
                aC[wi] = A_s[(wp + 1) * HC + ci];   // h_prev[w]
            }
            float w0[8], w1[8];
            *(float4*)&w0[0] = *(const float4*)&W_s[ci * 128 + co0];
            *(float4*)&w0[4] = *(const float4*)&W_s[ci * 128 + co0 + 4];
            *(float4*)&w1[0] = *(const float4*)&W_s[(128 + ci) * 128 + co0];
            *(float4*)&w1[4] = *(const float4*)&W_s[(128 + ci) * 128 + co0 + 4];
            #pragma unroll
            for (int wi = 0; wi < 4; wi++)
                #pragma unroll
                for (int c = 0; c < 8; c++)
                    acc[wi][c] += aL[wi] * w0[c] + aC[wi] * w1[c];
        }

        // ---- + bias + input conv, sigmoid, stash gates ----
        #pragma unroll
        for (int wi = 0; wi < 4; wi++) {
            int w = wi * 16 + i_;
            float xl[3], xc[3];
            #pragma unroll
            for (int cn = 0; cn < CIN; cn++) {
                xl[cn] = X_s[cn * 65 + w];        // x[w-1] (idx 0 = zero pad)
                xc[cn] = X_s[cn * 65 + w + 1];    // x[w]
            }
            #pragma unroll
            for (int c = 0; c < 8; c++) {
                int col = co0 + c;
                float v = acc[wi][c] + BI_s[col];
                #pragma unroll
                for (int cn = 0; cn < CIN; cn++)
                    v += xl[cn] * WI_s[cn * 128 + col] + xc[cn] * WI_s[384 + cn * 128 + col];
                v = 1.f / (1.f + __expf(-v));
                G_s[col * 65 + w] = v;
            }
        }
        __syncthreads();

        // ---- recombine gates -> c, h; write output row + next h-state ----
        float hv[8];
        #pragma unroll
        for (int q = 0; q < 8; q++) {
            int w = wb + q;
            float o  = G_s[(ci_l     ) * 65 + w];
            float f  = G_s[(32 + ci_l) * 65 + w];
            float ii = G_s[(64 + ci_l) * 65 + w];
            float g  = G_s[(96 + ci_l) * 65 + w];
            float cp = C_s[ci_l * 64 + w];
            float cn2 = f * cp + ii * g;
            C_s[ci_l * 64 + w] = cn2;
            hv[q] = o * tanhf(cn2);
        }
        float4* op = (float4*)&out[((b * HC + ci_g) * HH + s) * WW + wb];
        op[0] = make_float4(hv[0], hv[1], hv[2], hv[3]);
        op[1] = make_float4(hv[4], hv[5], hv[6], hv[7]);
        float* hw = g_h[1 - r] + b * WW * HC;
        #pragma unroll
        for (int q = 0; q < 8; q++) hw[(wb + q) * HC + ci_g] = hv[q];

        gsync();   // h-state for step s+1 visible everywhere
    }
}

extern "C" void kernel_launch(void* const* d_in, const int* in_sizes, int n_in,
                              void* d_out, int out_size) {
    const float* x    = (const float*)d_in[0];
    const float* W_is = (const float*)d_in[1];
    const float* b_is = (const float*)d_in[2];
    const float* W_ss = (const float*)d_in[3];
    const float* b_ss = (const float*)d_in[4];
    const float* h0   = (const float*)d_in[5];
    const float* c0   = (const float*)d_in[6];
    float* out = (float*)d_out;

    size_t smem = (size_t)SMEM_FLOATS * sizeof(float);
    cudaFuncSetAttribute(rowlstm_kernel,
                         cudaFuncAttributeMaxDynamicSharedMemorySize, (int)smem);
    rowlstm_kernel<<<NCTA, NTHR, smem>>>(x, W_is, b_is, W_ss, b_ss, h0, c0, out);
}

// round 3
// speedup vs baseline: 1.8338x; 1.8338x over previous
#include <cuda_runtime.h>
#include <cstdint>

#define BATCH 32
#define CIN   3
#define HH    64
#define WW    64
#define HC    128
#define NCTA  128
#define NTHR  256
#define CLU   4

// smem layout (floats). Two h tiles (double buffer), weights, input weights.
#define A0_OFF 0                    // (WW+1) x HC = 65*128 = 8320, row 0 = zero pad (w=-1)
#define A1_OFF 8320
#define W_OFF  16640                // 256 x 128 = 32768  (k = tap*128+ci, col = gate*32+ci_l)
#define WI_OFF 49408                // 2 x 3 x 128 = 768
#define SMEM_FLOATS 50176           // 200704 bytes

__device__ __forceinline__ unsigned long long pack2(float lo, float hi) {
    unsigned long long r;
    asm("mov.b64 %0, {%1, %2};" : "=l"(r) : "f"(lo), "f"(hi));
    return r;
}
__device__ __forceinline__ void unpack2(unsigned long long v, float& lo, float& hi) {
    asm("mov.b64 {%0, %1}, %2;" : "=f"(lo), "=f"(hi) : "l"(v));
}
__device__ __forceinline__ unsigned long long fma2(unsigned long long a,
                                                   unsigned long long b,
                                                   unsigned long long c) {
    unsigned long long d;
    asm("fma.rn.f32x2 %0, %1, %2, %3;" : "=l"(d) : "l"(a), "l"(b), "l"(c));
    return d;
}
__device__ __forceinline__ unsigned long long add2(unsigned long long a,
                                                   unsigned long long b) {
    unsigned long long d;
    asm("add.rn.f32x2 %0, %1, %2;" : "=l"(d) : "l"(a), "l"(b));
    return d;
}
__device__ __forceinline__ float sigm(float v) { return 1.f / (1.f + __expf(-v)); }

__global__ __launch_bounds__(NTHR, 1) __cluster_dims__(CLU, 1, 1)
void rowlstm_kernel(const float* __restrict__ x,
                    const float* __restrict__ W_is,
                    const float* __restrict__ b_is,
                    const float* __restrict__ W_ss,
                    const float* __restrict__ b_ss,
                    const float* __restrict__ h0,
                    const float* __restrict__ c0,
                    float* __restrict__ out)
{
    extern __shared__ float sm[];
    float* W_s  = sm + W_OFF;
    float* WI_s = sm + WI_OFF;

    const int tid = threadIdx.x;
    const int b   = blockIdx.x >> 2;
    unsigned int rank;
    asm("mov.u32 %0, %%cluster_ctarank;" : "=r"(rank));
    const int t = (int)rank;                 // ci-tile 0..3

    // ---- one-time loads ----
    // W_s[(tap*128+ci)*128 + col], col = gate*32 + ci_local
    for (int idx = tid; idx < 32768; idx += NTHR) {
        int k = idx >> 7, col = idx & 127;
        int tap = k >> 7, ci = k & 127;
        int co = (col >> 5) * HC + t * 32 + (col & 31);
        W_s[idx] = W_ss[(co * HC + ci) * 3 + tap];
    }
    for (int idx = tid; idx < 768; idx += NTHR) {
        int tap = idx / 384, rem = idx - tap * 384;
        int cin = rem >> 7, col = rem & 127;
        int co = (col >> 5) * HC + t * 32 + (col & 31);
        WI_s[idx] = W_is[(co * CIN + cin) * 3 + tap];
    }
    // A0 <- full h0 (all 128 ci), both pad rows zero
    for (int idx = tid; idx < 8192; idx += NTHR) {
        int w = idx >> 7, ci = idx & 127;
        sm[A0_OFF + (w + 1) * HC + ci] = h0[ci * WW + w];
    }
    for (int idx = tid; idx < HC; idx += NTHR) {
        sm[A0_OFF + idx] = 0.f;
        sm[A1_OFF + idx] = 0.f;
    }

    const int i_ = tid >> 4;          // 0..15 -> w lanes: w = wi*16 + i_
    const int j_ = tid & 15;          // 0..15 -> ci pair j2 = 2*j_
    const int j2 = j_ << 1;

    // per-thread persistent state: bias pairs + cell state registers
    unsigned long long bias2[4];
    #pragma unroll
    for (int g = 0; g < 4; g++) {
        int co = g * HC + t * 32 + j2;
        bias2[g] = pack2(b_is[co] + b_ss[co], b_is[co + 1] + b_ss[co + 1]);
    }
    float creg[4][2];
    #pragma unroll
    for (int wi = 0; wi < 4; wi++) {
        int w = wi * 16 + i_;
        creg[wi][0] = c0[(t * 32 + j2) * WW + w];
        creg[wi][1] = c0[(t * 32 + j2 + 1) * WW + w];
    }

    // peer smem base addresses (shared::cluster window) for DSMEM h exchange
    unsigned int mybase;
    asm("{ .reg .u64 a; cvta.to.shared.u64 a, %1; cvt.u32.u64 %0, a; }"
        : "=r"(mybase) : "l"(sm));
    unsigned int peer[CLU];
    #pragma unroll
    for (int r = 0; r < CLU; r++)
        asm("mapa.shared::cluster.u32 %0, %1, %2;" : "=r"(peer[r]) : "r"(mybase), "r"(r));

    __syncthreads();   // local init (W_s, WI_s, A0) visible block-wide

    for (int s = 0; s < HH; s++) {
        const float* Ac = sm + ((s & 1) ? A1_OFF : A0_OFF);
        const unsigned int nextOffB = (unsigned int)(((s & 1) ? A0_OFF : A1_OFF) * 4);

        // ---- GEMM: gates for (4 w) x (4 gates x 2 ci) over K = 2 taps x 128 ci ----
        unsigned long long acc[4][4];
        #pragma unroll
        for (int wi = 0; wi < 4; wi++)
            #pragma unroll
            for (int g = 0; g < 4; g++) acc[wi][g] = 0ULL;

        for (int cb = 0; cb < HC; cb += 4) {
            float4 aL4[4], aC4[4];
            #pragma unroll
            for (int wi = 0; wi < 4; wi++) {
                int wp = wi * 16 + i_;
                aL4[wi] = *(const float4*)(Ac + wp * HC + cb);
                aC4[wi] = *(const float4*)(Ac + (wp + 1) * HC + cb);
            }
            #pragma unroll
            for (int u = 0; u < 4; u++) {
                const float* wr0 = W_s + (cb + u) * 128 + j2;
                const float* wr1 = wr0 + 128 * 128;
                unsigned long long w0p[4], w1p[4];
                #pragma unroll
                for (int g = 0; g < 4; g++) {
                    w0p[g] = *(const unsigned long long*)(wr0 + g * 32);
                    w1p[g] = *(const unsigned long long*)(wr1 + g * 32);
                }
                unsigned long long aLp[4], aCp[4];
                #pragma unroll
                for (int wi = 0; wi < 4; wi++) {
                    float aL = ((const float*)&aL4[wi])[u];
                    float aC = ((const float*)&aC4[wi])[u];
                    aLp[wi] = pack2(aL, aL);
                    aCp[wi] = pack2(aC, aC);
                }
                #pragma unroll
                for (int wi = 0; wi < 4; wi++)
                    #pragma unroll
                    for (int g = 0; g < 4; g++)
                        acc[wi][g] = fma2(aLp[wi], w0p[g], acc[wi][g]);
                #pragma unroll
                for (int wi = 0; wi < 4; wi++)
                    #pragma unroll
                    for (int g = 0; g < 4; g++)
                        acc[wi][g] = fma2(aCp[wi], w1p[g], acc[wi][g]);
            }
        }

        // ---- x-projection (3 cin x 2 taps) + bias ----
        float xr[4][3][2];
        #pragma unroll
        for (int wi = 0; wi < 4; wi++) {
            int w = wi * 16 + i_;
            #pragma unroll
            for (int cn = 0; cn < CIN; cn++) {
                const float* xb = x + ((b * CIN + cn) * HH + s) * WW;
                xr[wi][cn][0] = (w > 0) ? xb[w - 1] : 0.f;
                xr[wi][cn][1] = xb[w];
            }
        }
        unsigned long long xadd[4][4];
        #pragma unroll
        for (int wi = 0; wi < 4; wi++)
            #pragma unroll
            for (int g = 0; g < 4; g++) xadd[wi][g] = bias2[g];
        #pragma unroll
        for (int cn = 0; cn < CIN; cn++)
            #pragma unroll
            for (int tap = 0; tap < 2; tap++) {
                unsigned long long wp_[4];
                #pragma unroll
                for (int g = 0; g < 4; g++)
                    wp_[g] = *(const unsigned long long*)(WI_s + tap * 384 + cn * 128 + g * 32 + j2);
                #pragma unroll
                for (int wi = 0; wi < 4; wi++) {
                    unsigned long long xp = pack2(xr[wi][cn][tap], xr[wi][cn][tap]);
                    #pragma unroll
                    for (int g = 0; g < 4; g++)
                        xadd[wi][g] = fma2(xp, wp_[g], xadd[wi][g]);
                }
            }

        // ---- gates -> c,h in registers; write out + h to all 4 cluster CTAs ----
        #pragma unroll
        for (int wi = 0; wi < 4; wi++) {
            int w = wi * 16 + i_;
            float gv[4][2];
            #pragma unroll
            for (int g = 0; g < 4; g++) {
                float a0, a1;
                unpack2(add2(acc[wi][g], xadd[wi][g]), a0, a1);
                gv[g][0] = sigm(a0);
                gv[g][1] = sigm(a1);
            }
            float hp[2];
            #pragma unroll
            for (int p = 0; p < 2; p++) {
                float cn2 = gv[1][p] * creg[wi][p] + gv[2][p] * gv[3][p];
                creg[wi][p] = cn2;
                float h = gv[0][p] * tanhf(cn2);
                hp[p] = h;
                out[((b * HC + t * 32 + j2 + p) * HH + s) * WW + w] = h;
            }
            unsigned long long hpair = pack2(hp[0], hp[1]);
            unsigned int off = nextOffB + (unsigned int)(((w + 1) * HC + t * 32 + j2) * 4);
            #pragma unroll
            for (int r = 0; r < CLU; r++)
                asm volatile("st.shared::cluster.b64 [%0], %1;"
                             :: "r"(peer[r] + off), "l"(hpair) : "memory");
        }

        // one cluster barrier per step: h(s) visible in everyone's A_next
        asm volatile("barrier.cluster.arrive.aligned;" ::: "memory");
        asm volatile("barrier.cluster.wait.aligned;" ::: "memory");
    }
}

extern "C" void kernel_launch(void* const* d_in, const int* in_sizes, int n_in,
                              void* d_out, int out_size) {
    const float* x    = (const float*)d_in[0];
    const float* W_is = (const float*)d_in[1];
    const float* b_is = (const float*)d_in[2];
    const float* W_ss = (const float*)d_in[3];
    const float* b_ss = (const float*)d_in[4];
    const float* h0   = (const float*)d_in[5];
    const float* c0   = (const float*)d_in[6];
    float* out = (float*)d_out;

    size_t smem = (size_t)SMEM_FLOATS * sizeof(float);
    cudaFuncSetAttribute(rowlstm_kernel,
                         cudaFuncAttributeMaxDynamicSharedMemorySize, (int)smem);
    rowlstm_kernel<<<NCTA, NTHR, smem>>>(x, W_is, b_is, W_ss, b_ss, h0, c0, out);
}